// round 6
// baseline (speedup 1.0000x reference)
#include <cuda_runtime.h>
#include <cuda_bf16.h>

#define N_PTS   32768
#define S_NBR   32
#define C_IN    64
#define C_OUT   128
#define NS      (N_PTS * S_NBR)   // 1048576
#define EPSBN   1e-5f

typedef unsigned long long ull;

// Scratch (device globals; no allocation allowed)
__device__ float g_agg [C_IN  * N_PTS];   // [c][n]  8 MB
__device__ float g_ypre[C_OUT * N_PTS];   // [o][n] 16 MB  (feature pre-BN)
__device__ float g_rpre[C_OUT * N_PTS];   // [o][n] 16 MB  (residual pre-BN)
__device__ float g_cA[2 * C_OUT];         // BN scale  [feat | res]
__device__ float g_cB[2 * C_OUT];         // BN shift  [feat | res]

// ---- packed f32x2 helpers ----
__device__ __forceinline__ ull pack2(float lo, float hi) {
    ull r;
    asm("mov.b64 %0, {%1, %2};" : "=l"(r) : "f"(lo), "f"(hi));
    return r;
}
__device__ __forceinline__ void ffma2(ull& d, ull a, ull b) {
    asm("fma.rn.f32x2 %0, %1, %2, %3;" : "=l"(d) : "l"(a), "l"(b), "l"(d));
}

// ---------------------------------------------------------------------------
// Aggregation only (slim, high-occupancy). Block = 256 threads, 32 points.
// lane = (idx = lane>>3, s4 = lane&7); warp w owns channels [8w, 8w+8).
// Point-group outer (positions register-resident), channel inner.
// LDG.128 per warp = 512B contiguous. 3-shfl reduce over the 8-lane group.
__global__ __launch_bounds__(256, 4) void k_agg(
    const float* __restrict__ xyz,     // [N][3]
    const float* __restrict__ np,      // [67][N][S]
    const float* __restrict__ Wint,    // [64][3]
    const float* __restrict__ bint)    // [64]
{
    __shared__ __align__(16) float spos[3 * 32 * 32];  // 12 KB: [k][pt][s]
    __shared__ float  aggs[C_IN][33];                  // padded
    __shared__ float4 wq[C_IN];                        // {w0,w1,w2,bias}

    int tid  = threadIdx.x;
    int warp = tid >> 5;
    int lane = tid & 31;
    int n0   = blockIdx.x * 32;

    if (tid < C_IN)
        wq[tid] = make_float4(Wint[tid*3+0], Wint[tid*3+1], Wint[tid*3+2], bint[tid]);
    #pragma unroll
    for (int i = tid; i < 3 * 1024; i += 256) {
        int k  = i >> 10;          // coord 0..2
        int r  = i & 1023;         // pt*32 + s
        int pt = r >> 5;
        spos[i] = np[k * NS + (n0 << 5) + r] - xyz[(n0 + pt) * 3 + k];
    }
    __syncthreads();

    {
        int s4  = lane & 7;        // 16B chunk within a 128B s-line
        int idx = lane >> 3;       // point within group of 4
        int c0  = warp << 3;       // first channel this warp owns
        const float4* sp4 = (const float4*)spos;

        #pragma unroll
        for (int ptg = 0; ptg < 8; ptg++) {
            int pt = (ptg << 2) | idx;
            float4 px = sp4[0 * 256 + (pt << 3) + s4];
            float4 py = sp4[1 * 256 + (pt << 3) + s4];
            float4 pz = sp4[2 * 256 + (pt << 3) + s4];

            const float* fb = np + (size_t)3 * NS
                            + (((size_t)(n0 + pt)) << 5) + (s4 << 2);

            #pragma unroll
            for (int ci = 0; ci < 8; ci++) {
                int c = c0 | ci;
                float4 w = wq[c];                                  // broadcast
                float4 f = *(const float4*)(fb + (size_t)c * NS);  // 512B/warp

                float h0 = fmaf(w.x, px.x, fmaf(w.y, py.x, fmaf(w.z, pz.x, w.w)));
                float h1 = fmaf(w.x, px.y, fmaf(w.y, py.y, fmaf(w.z, pz.y, w.w)));
                float h2 = fmaf(w.x, px.z, fmaf(w.y, py.z, fmaf(w.z, pz.z, w.w)));
                float h3 = fmaf(w.x, px.w, fmaf(w.y, py.w, fmaf(w.z, pz.w, w.w)));

                float acc;
                acc = fmaxf(h0, 0.0f) * f.x;
                acc = fmaf(fmaxf(h1, 0.0f), f.y, acc);
                acc = fmaf(fmaxf(h2, 0.0f), f.z, acc);
                acc = fmaf(fmaxf(h3, 0.0f), f.w, acc);

                acc += __shfl_xor_sync(0xffffffffu, acc, 1);
                acc += __shfl_xor_sync(0xffffffffu, acc, 2);
                acc += __shfl_xor_sync(0xffffffffu, acc, 4);
                if (s4 == 0) aggs[c][pt] = acc;
            }
        }
    }
    __syncthreads();

    // coalesced transposed write: g_agg[c][n0..n0+31]
    #pragma unroll
    for (int i = tid; i < C_IN * 32; i += 256) {
        int c = i >> 5, col = i & 31;
        g_agg[c * N_PTS + n0 + col] = aggs[c][col];
    }
}

// ---------------------------------------------------------------------------
// Packed GEMV 64 -> 128. Block = 256 threads, 64 points.
// Warp = 16-output slab; lane = point PAIR (2 points packed in f32x2).
// Weights pre-duplicated {w,w} in 64 KB dynamic smem -> every inner op is
// one broadcast LDS.64 + one FFMA2 (half the fma-pipe issue of scalar).
// SEL=0: feature path (g_agg -> g_ypre). SEL=1: residual (pf -> g_rpre).
template<int SEL>
__global__ __launch_bounds__(256) void k_gemv(
    const float* __restrict__ in_ext,  // used when SEL==1
    const float* __restrict__ W,       // [128][64]
    const float* __restrict__ b)       // [128]
{
    extern __shared__ ull Wdup[];                // [128][64] = 64 KB
    __shared__ float ftile[C_IN][64];            // 16 KB

    int tid  = threadIdx.x;
    int warp = tid >> 5;
    int lane = tid & 31;
    int n0   = blockIdx.x * 64;

    const float* __restrict__ in = (SEL == 0) ? (const float*)g_agg : in_ext;

    // stage duplicated weights (coalesced LDG, STS.64)
    #pragma unroll
    for (int i = tid; i < C_OUT * C_IN; i += 256) {
        float w = W[i];
        Wdup[i] = pack2(w, w);
    }
    // stage input tile [64 ch][64 pts] via float4
    #pragma unroll
    for (int i4 = tid; i4 < C_IN * 16; i4 += 256) {
        int c = i4 >> 4, col4 = i4 & 15;
        ((float4*)ftile[c])[col4] = *(const float4*)(in + c * N_PTS + n0 + col4 * 4);
    }
    __syncthreads();

    int o0 = warp * 16;
    ull acc2[16];
    #pragma unroll
    for (int oi = 0; oi < 16; oi++) {
        float bv = b[o0 + oi];
        acc2[oi] = pack2(bv, bv);
    }

    #pragma unroll 4
    for (int c = 0; c < C_IN; c++) {
        ull f2 = ((const ull*)ftile[c])[lane];          // 2 adjacent points
        const ull* wrow = &Wdup[o0 * C_IN + c];
        #pragma unroll
        for (int oi = 0; oi < 16; oi++) {
            ull w2 = wrow[oi * C_IN];                   // broadcast LDS.64
            ffma2(acc2[oi], f2, w2);
        }
    }

    float* outp = (SEL == 0) ? g_ypre : g_rpre;
    #pragma unroll
    for (int oi = 0; oi < 16; oi++)
        ((ull*)(outp + (o0 + oi) * N_PTS + n0))[lane] = acc2[oi];   // 256B/row
}

// ---------------------------------------------------------------------------
// BN stats: one block per (channel, path). No atomics. Emits scale/shift.
__global__ __launch_bounds__(256) void k_stats(
    const float* __restrict__ gf, const float* __restrict__ btf,
    const float* __restrict__ gr, const float* __restrict__ btr)
{
    __shared__ float ws1[8], ws2[8];

    int o   = blockIdx.x & (C_OUT - 1);
    int buf = blockIdx.x >> 7;
    int tid = threadIdx.x;

    const float4* src = (const float4*)((buf ? g_rpre : g_ypre) + o * N_PTS);

    float s1 = 0.0f, s2 = 0.0f;
    #pragma unroll 4
    for (int i = tid; i < N_PTS/4; i += 256) {
        float4 v = src[i];
        s1 += v.x + v.y + v.z + v.w;
        s2 += v.x*v.x + v.y*v.y + v.z*v.z + v.w*v.w;
    }
    #pragma unroll
    for (int off = 16; off; off >>= 1) {
        s1 += __shfl_xor_sync(0xffffffffu, s1, off);
        s2 += __shfl_xor_sync(0xffffffffu, s2, off);
    }
    int warp = tid >> 5, lane = tid & 31;
    if (lane == 0) { ws1[warp] = s1; ws2[warp] = s2; }
    __syncthreads();
    if (tid == 0) {
        float t1 = 0.0f, t2 = 0.0f;
        #pragma unroll
        for (int w = 0; w < 8; w++) { t1 += ws1[w]; t2 += ws2[w]; }
        const float inv = 1.0f / (float)N_PTS;
        float mean = t1 * inv;
        float var  = t2 * inv - mean * mean;
        float gamma = buf ? gr[o] : gf[o];
        float beta  = buf ? btr[o] : btf[o];
        float A = gamma * rsqrtf(var + EPSBN);
        g_cA[buf * C_OUT + o] = A;
        g_cB[buf * C_OUT + o] = beta - mean * A;
    }
}

// ---------------------------------------------------------------------------
// Finalize: BN affine + ReLU on both paths, add, float4 throughout.
__global__ __launch_bounds__(256) void k_final(float* __restrict__ out)
{
    int i4 = blockIdx.x * 256 + threadIdx.x;    // float4 index
    int o  = i4 >> 13;                          // channel (N/4 = 8192 per row)

    float Af = g_cA[o],         Bf = g_cB[o];
    float Ar = g_cA[C_OUT + o], Br = g_cB[C_OUT + o];

    float4 y = ((const float4*)g_ypre)[i4];
    float4 r = ((const float4*)g_rpre)[i4];
    float4 v;
    v.x = fmaxf(fmaf(y.x, Af, Bf), 0.0f) + fmaxf(fmaf(r.x, Ar, Br), 0.0f);
    v.y = fmaxf(fmaf(y.y, Af, Bf), 0.0f) + fmaxf(fmaf(r.y, Ar, Br), 0.0f);
    v.z = fmaxf(fmaf(y.z, Af, Bf), 0.0f) + fmaxf(fmaf(r.z, Ar, Br), 0.0f);
    v.w = fmaxf(fmaf(y.w, Af, Bf), 0.0f) + fmaxf(fmaf(r.w, Ar, Br), 0.0f);
    ((float4*)out)[i4] = v;
}

// ---------------------------------------------------------------------------
extern "C" void kernel_launch(void* const* d_in, const int* in_sizes, int n_in,
                              void* d_out, int out_size) {
    const float* xyz   = (const float*)d_in[0];   // (1, N, 3)
    const float* pf    = (const float*)d_in[1];   // (1, 64, N)
    const float* np    = (const float*)d_in[2];   // (1, 67, N, 32)
    const float* Wint  = (const float*)d_in[3];
    const float* bint  = (const float*)d_in[4];
    const float* Wfeat = (const float*)d_in[5];
    const float* bfeat = (const float*)d_in[6];
    const float* gfeat = (const float*)d_in[7];
    const float* befeat= (const float*)d_in[8];
    const float* Wres  = (const float*)d_in[9];
    const float* bres  = (const float*)d_in[10];
    const float* gres  = (const float*)d_in[11];
    const float* beres = (const float*)d_in[12];
    float* out = (float*)d_out;

    const int WDUP_BYTES = C_OUT * C_IN * (int)sizeof(ull);   // 64 KB
    static bool attr_done = false;
    if (!attr_done) {
        cudaFuncSetAttribute(k_gemv<0>, cudaFuncAttributeMaxDynamicSharedMemorySize, WDUP_BYTES);
        cudaFuncSetAttribute(k_gemv<1>, cudaFuncAttributeMaxDynamicSharedMemorySize, WDUP_BYTES);
        attr_done = true;
    }

    k_agg<<<N_PTS / 32, 256>>>(xyz, np, Wint, bint);
    k_gemv<1><<<N_PTS / 64, 256, WDUP_BYTES>>>(pf, Wres, bres);
    k_gemv<0><<<N_PTS / 64, 256, WDUP_BYTES>>>(nullptr, Wfeat, bfeat);
    k_stats<<<2 * C_OUT, 256>>>(gfeat, befeat, gres, beres);
    k_final<<<(C_OUT * N_PTS / 4) / 256, 256>>>(out);
}